// round 15
// baseline (speedup 1.0000x reference)
#include <cuda_runtime.h>
#include <cuda_fp16.h>

#define LVLS 16
#define TSIZE 16384
#define NPTS 262144
#define NPAIRS (NPTS / 2)
#define TMASK 16383
#define PRIME1 (-1640531535)   // 2654435761 wrapped to int32
#define PRIME2 (805459861)
#define CTAS_PER_LVL 9
#define NTHREADS 1024
#define TPTS 256               // points per transpose tile
#define TPITCH 17              // level pitch in transpose tile
#define FSCALE 8192.0f         // exact power of two: scaling is lossless in fp32
#define INVSCALE (1.0f / 8192.0f)

// Scratch in (L, N) layout of half2 — 16.75MB static device array (allowed).
// Values are pre-scaled by FSCALE so all magnitudes sit in fp16 normal range.
__device__ __half2 g_scr[(size_t)LVLS * NPTS];

// ---------------------------------------------------------------------------
// Per-point hash-grid computation (identical arithmetic to the passing
// kernels — index math must stay bit-exact).
// ---------------------------------------------------------------------------
__device__ __forceinline__ float2 hash_point(const float2* __restrict__ table,
                                             float x0, float x1, float x2,
                                             float scale)
{
    const float u0 = x0 * scale, u1 = x1 * scale, u2 = x2 * scale;
    const float f0 = floorf(u0), f1 = floorf(u1), f2 = floorf(u2);
    const int   i0 = (int)f0,    i1 = (int)f1,    i2 = (int)f2;
    // d = ceil-floor is 1 when frac>0, else 0 -> diff == frac either way.
    const float d0 = u0 - f0, d1 = u1 - f1, d2 = u2 - f2;
    const float o0 = 1.0f - d0, o1 = 1.0f - d1, o2 = 1.0f - d2;

    // Pre-multiplied corner hash terms (wrapping int32, matches jnp/torch)
    const int pl0 = i0;                  const int ph0 = pl0 + 1;
    const int pl1 = i1 * PRIME1;         const int ph1 = pl1 + PRIME1;
    const int pl2 = i2 * PRIME2;         const int ph2 = pl2 + PRIME2;
    // frac==0 corners carry an exactly-zero weight, so hi = lo+1 is safe.

    float ax = 0.0f, ay = 0.0f;
    #pragma unroll
    for (int k = 0; k < 8; ++k) {
        const int a  = (k >> 2) & 1;
        const int b  = (k >> 1) & 1;
        const int c  = k & 1;
        const int h = (a ? ph0 : pl0) ^ (b ? ph1 : pl1) ^ (c ? ph2 : pl2);
        const int idx = h & TMASK;      // == mod 16384 for int32
        const float w = (a ? d0 : o0) * (b ? d1 : o1) * (c ? d2 : o2);
        const float2 v = table[idx];
        ax = fmaf(w, v.x, ax);
        ay = fmaf(w, v.y, ay);
    }
    return make_float2(ax, ay);
}

// ---------------------------------------------------------------------------
// Kernel 1: hash-grid gather, 2 points per thread. One CTA per (level,
// slice); the level's 128KB table lives in shared memory. Results are stored
// to fp16 scratch (scaled by FSCALE), 8B per thread, 256B/warp coalesced.
// ---------------------------------------------------------------------------
__global__ __launch_bounds__(NTHREADS, 1)
void hash_enc_kernel(const float* __restrict__ x,
                     const float* __restrict__ emb)
{
    extern __shared__ float2 table[];   // TSIZE float2 = 128KB
    const int level = blockIdx.y;

    // Cooperative table load (float4-vectorized, coalesced)
    {
        const float4* src = (const float4*)(emb + (size_t)level * TSIZE * 2);
        float4* dst = (float4*)table;
        #pragma unroll
        for (int i = threadIdx.x; i < (TSIZE * 2) / 4; i += NTHREADS)
            dst[i] = src[i];
    }
    __syncthreads();

    // Per-level resolution: N_l = Nmin * b^l (identical formula)
    const float bgrow = expf((logf(512.0f) - logf(16.0f)) * (1.0f / 16.0f));
    const float scale = 16.0f * powf(bgrow, (float)level);

    const float2* x2 = (const float2*)x;
    __half2* scr = g_scr + (size_t)level * NPTS;

    const int stride = CTAS_PER_LVL * NTHREADS;
    for (int p = blockIdx.x * NTHREADS + threadIdx.x; p < NPAIRS; p += stride) {
        // 6 floats = points 2p and 2p+1, three aligned float2 loads
        const float2 va = x2[3 * p + 0];   // xA0, xA1
        const float2 vb = x2[3 * p + 1];   // xA2, xB0
        const float2 vc = x2[3 * p + 2];   // xB1, xB2

        const float2 rA = hash_point(table, va.x, va.y, vb.x, scale);
        const float2 rB = hash_point(table, vb.y, vc.x, vc.y, scale);

        // Scale into fp16 normal range (x8192 exact), pack two points -> 8B
        union { __half2 h[2]; uint2 u; } pk;
        pk.h[0] = __floats2half2_rn(rA.x * FSCALE, rA.y * FSCALE);
        pk.h[1] = __floats2half2_rn(rB.x * FSCALE, rB.y * FSCALE);
        *(uint2*)(scr + 2 * p) = pk.u;
    }
}

// ---------------------------------------------------------------------------
// Kernel 2: (L, N) half2 -> (N, L*2) fp32 transpose. Thread t loads level l's
// half2 for point n0+t (warp: 128B contiguous), converts to fp32 (x1/8192,
// exact), tiles in smem, and writes 512B-contiguous STG.128 output rows.
// ---------------------------------------------------------------------------
__global__ __launch_bounds__(TPTS)
void transpose_kernel(float* __restrict__ out)
{
    __shared__ float2 tile[TPTS][TPITCH];   // 256 x 17 x 8B = 34.8KB

    const int n0 = blockIdx.x * TPTS;
    const int t  = threadIdx.x;

    #pragma unroll
    for (int l = 0; l < LVLS; ++l) {
        const __half2 h = g_scr[(size_t)l * NPTS + n0 + t];
        const float2 f = __half22float2(h);
        tile[t][l] = make_float2(f.x * INVSCALE, f.y * INVSCALE);
    }
    __syncthreads();

    // Store: warp writes 4 consecutive 128B output rows per pass.
    const int q  = t & 7;    // float4 (pair of levels) within the row
    const int pl = t >> 3;   // point-within-tile offset
    float4* out4 = (float4*)out;
    #pragma unroll
    for (int i = 0; i < TPTS / 32; ++i) {
        const int p = i * 32 + pl;
        const float2 a = tile[p][2 * q];
        const float2 b = tile[p][2 * q + 1];
        out4[(size_t)(n0 + p) * (LVLS / 2) + q] = make_float4(a.x, a.y, b.x, b.y);
    }
}

extern "C" void kernel_launch(void* const* d_in, const int* in_sizes, int n_in,
                              void* d_out, int out_size)
{
    const float* x;
    const float* emb;
    if (in_sizes[0] == NPTS * 3) {
        x = (const float*)d_in[0];
        emb = (const float*)d_in[1];
    } else {
        x = (const float*)d_in[1];
        emb = (const float*)d_in[0];
    }
    float* out = (float*)d_out;

    cudaFuncSetAttribute(hash_enc_kernel,
                         cudaFuncAttributeMaxDynamicSharedMemorySize,
                         TSIZE * 2 * (int)sizeof(float));

    dim3 grid(CTAS_PER_LVL, LVLS);   // 144 CTAs = one full wave @ 1 CTA/SM
    hash_enc_kernel<<<grid, NTHREADS, TSIZE * 2 * sizeof(float)>>>(x, emb);

    transpose_kernel<<<NPTS / TPTS, TPTS>>>(out);
}

// round 16
// speedup vs baseline: 1.0418x; 1.0418x over previous
#include <cuda_runtime.h>
#include <cuda_fp16.h>

#define LVLS 16
#define TSIZE 16384
#define NPTS 262144
#define NPAIRS (NPTS / 2)
#define TMASK 16383
#define PRIME1 (-1640531535)   // 2654435761 wrapped to int32
#define PRIME2 (805459861)
#define CTAS_PER_LVL 9
#define NTHREADS 1024
#define TPTS 256               // points per transpose tile
#define TPITCH 17              // level pitch in transpose tile
#define FSCALE 8192.0f         // exact power of two: scaling is lossless in fp32
#define INVSCALE (1.0f / 8192.0f)

// Scratch in (L, N) layout of half2 — 16.75MB static device array (allowed).
// Values are pre-scaled by FSCALE so all magnitudes sit in fp16 normal range.
__device__ __half2 g_scr[(size_t)LVLS * NPTS];

// Pack two fp32 into one f16x2 register directly (no memory round-trip).
// First source -> HIGH half, second -> LOW half (PTX cvt packing order),
// so lo = c0 matches the __half2{x=lo,y=hi} layout read by the transpose.
__device__ __forceinline__ unsigned int pack_f16x2(float lo, float hi)
{
    unsigned int r;
    asm("cvt.rn.f16x2.f32 %0, %1, %2;" : "=r"(r) : "f"(hi), "f"(lo));
    return r;
}

// ---------------------------------------------------------------------------
// Per-point hash-grid computation (identical arithmetic to the passing
// kernels — index math must stay bit-exact).
// ---------------------------------------------------------------------------
__device__ __forceinline__ float2 hash_point(const float2* __restrict__ table,
                                             float x0, float x1, float x2,
                                             float scale)
{
    const float u0 = x0 * scale, u1 = x1 * scale, u2 = x2 * scale;
    const float f0 = floorf(u0), f1 = floorf(u1), f2 = floorf(u2);
    const int   i0 = (int)f0,    i1 = (int)f1,    i2 = (int)f2;
    // d = ceil-floor is 1 when frac>0, else 0 -> diff == frac either way.
    const float d0 = u0 - f0, d1 = u1 - f1, d2 = u2 - f2;
    const float o0 = 1.0f - d0, o1 = 1.0f - d1, o2 = 1.0f - d2;

    // Pre-multiplied corner hash terms (wrapping int32, matches jnp/torch)
    const int pl0 = i0;                  const int ph0 = pl0 + 1;
    const int pl1 = i1 * PRIME1;         const int ph1 = pl1 + PRIME1;
    const int pl2 = i2 * PRIME2;         const int ph2 = pl2 + PRIME2;
    // frac==0 corners carry an exactly-zero weight, so hi = lo+1 is safe.

    float ax = 0.0f, ay = 0.0f;
    #pragma unroll
    for (int k = 0; k < 8; ++k) {
        const int a  = (k >> 2) & 1;
        const int b  = (k >> 1) & 1;
        const int c  = k & 1;
        const int h = (a ? ph0 : pl0) ^ (b ? ph1 : pl1) ^ (c ? ph2 : pl2);
        const int idx = h & TMASK;      // == mod 16384 for int32
        const float w = (a ? d0 : o0) * (b ? d1 : o1) * (c ? d2 : o2);
        const float2 v = table[idx];
        ax = fmaf(w, v.x, ax);
        ay = fmaf(w, v.y, ay);
    }
    return make_float2(ax, ay);
}

// ---------------------------------------------------------------------------
// Kernel 1: hash-grid gather, 2 points per thread. One CTA per (level,
// slice); the level's 128KB table lives in shared memory. Results packed to
// fp16x2 IN REGISTERS (cvt.rn.f16x2.f32) and stored as one 8B uint2,
// 256B/warp coalesced.
// ---------------------------------------------------------------------------
__global__ __launch_bounds__(NTHREADS, 1)
void hash_enc_kernel(const float* __restrict__ x,
                     const float* __restrict__ emb)
{
    extern __shared__ float2 table[];   // TSIZE float2 = 128KB
    const int level = blockIdx.y;

    // Cooperative table load (float4-vectorized, coalesced)
    {
        const float4* src = (const float4*)(emb + (size_t)level * TSIZE * 2);
        float4* dst = (float4*)table;
        #pragma unroll
        for (int i = threadIdx.x; i < (TSIZE * 2) / 4; i += NTHREADS)
            dst[i] = src[i];
    }
    __syncthreads();

    // Per-level resolution: N_l = Nmin * b^l (identical formula)
    const float bgrow = expf((logf(512.0f) - logf(16.0f)) * (1.0f / 16.0f));
    const float scale = 16.0f * powf(bgrow, (float)level);

    const float2* x2 = (const float2*)x;
    __half2* scr = g_scr + (size_t)level * NPTS;

    const int stride = CTAS_PER_LVL * NTHREADS;
    for (int p = blockIdx.x * NTHREADS + threadIdx.x; p < NPAIRS; p += stride) {
        // 6 floats = points 2p and 2p+1, three aligned float2 loads
        const float2 va = x2[3 * p + 0];   // xA0, xA1
        const float2 vb = x2[3 * p + 1];   // xA2, xB0
        const float2 vc = x2[3 * p + 2];   // xB1, xB2

        const float2 rA = hash_point(table, va.x, va.y, vb.x, scale);
        const float2 rB = hash_point(table, vb.y, vc.x, vc.y, scale);

        // Scale into fp16 normal range (x8192 exact), pack in registers
        const unsigned int uA = pack_f16x2(rA.x * FSCALE, rA.y * FSCALE);
        const unsigned int uB = pack_f16x2(rB.x * FSCALE, rB.y * FSCALE);
        *(uint2*)(scr + 2 * p) = make_uint2(uA, uB);
    }
}

// ---------------------------------------------------------------------------
// Kernel 2: (L, N) half2 -> (N, L*2) fp32 transpose. Thread t loads level l's
// half2 for point n0+t (warp: 128B contiguous), converts to fp32 (x1/8192,
// exact), tiles in smem, and writes 512B-contiguous STG.128 output rows.
// ---------------------------------------------------------------------------
__global__ __launch_bounds__(TPTS)
void transpose_kernel(float* __restrict__ out)
{
    __shared__ float2 tile[TPTS][TPITCH];   // 256 x 17 x 8B = 34.8KB

    const int n0 = blockIdx.x * TPTS;
    const int t  = threadIdx.x;

    #pragma unroll
    for (int l = 0; l < LVLS; ++l) {
        const __half2 h = g_scr[(size_t)l * NPTS + n0 + t];
        const float2 f = __half22float2(h);
        tile[t][l] = make_float2(f.x * INVSCALE, f.y * INVSCALE);
    }
    __syncthreads();

    // Store: warp writes 4 consecutive 128B output rows per pass.
    const int q  = t & 7;    // float4 (pair of levels) within the row
    const int pl = t >> 3;   // point-within-tile offset
    float4* out4 = (float4*)out;
    #pragma unroll
    for (int i = 0; i < TPTS / 32; ++i) {
        const int p = i * 32 + pl;
        const float2 a = tile[p][2 * q];
        const float2 b = tile[p][2 * q + 1];
        out4[(size_t)(n0 + p) * (LVLS / 2) + q] = make_float4(a.x, a.y, b.x, b.y);
    }
}

extern "C" void kernel_launch(void* const* d_in, const int* in_sizes, int n_in,
                              void* d_out, int out_size)
{
    const float* x;
    const float* emb;
    if (in_sizes[0] == NPTS * 3) {
        x = (const float*)d_in[0];
        emb = (const float*)d_in[1];
    } else {
        x = (const float*)d_in[1];
        emb = (const float*)d_in[0];
    }
    float* out = (float*)d_out;

    cudaFuncSetAttribute(hash_enc_kernel,
                         cudaFuncAttributeMaxDynamicSharedMemorySize,
                         TSIZE * 2 * (int)sizeof(float));

    dim3 grid(CTAS_PER_LVL, LVLS);   // 144 CTAs = one full wave @ 1 CTA/SM
    hash_enc_kernel<<<grid, NTHREADS, TSIZE * 2 * sizeof(float)>>>(x, emb);

    transpose_kernel<<<NPTS / TPTS, TPTS>>>(out);
}

// round 17
// speedup vs baseline: 1.1105x; 1.0660x over previous
#include <cuda_runtime.h>
#include <cuda_fp16.h>

#define LVLS 16
#define TSIZE 16384
#define NPTS 262144
#define NQUADS (NPTS / 4)
#define TMASK 16383
#define PRIME1 (-1640531535)   // 2654435761 wrapped to int32
#define PRIME2 (805459861)
#define CTAS_PER_LVL 9
#define NTHREADS 1024
#define TPTS 256               // points per transpose tile
#define TPITCH 17              // level pitch in transpose tile
#define FSCALE 8192.0f         // 2^13: exact exponent shift in fp32
#define INVSCALE (1.0f / 8192.0f)

// Scratch in (L, N) layout of half2 — 16.75MB static device array (allowed).
// Values are pre-scaled by FSCALE (via the pre-scaled table) so all
// magnitudes sit in fp16 normal range.
__device__ __half2 g_scr[(size_t)LVLS * NPTS];

// Pack two fp32 into one f16x2 register (no memory round-trip).
// PTX packing: first source -> HIGH half, second -> LOW half.
__device__ __forceinline__ unsigned int pack_f16x2(float lo, float hi)
{
    unsigned int r;
    asm("cvt.rn.f16x2.f32 %0, %1, %2;" : "=r"(r) : "f"(hi), "f"(lo));
    return r;
}

// ---------------------------------------------------------------------------
// Per-point hash-grid computation. Index math is bit-exact vs the reference;
// the table holds 8192*emb (exact power-of-2 scale), so the returned features
// are exactly 8192x the reference features.
// ---------------------------------------------------------------------------
__device__ __forceinline__ float2 hash_point(const float2* __restrict__ table,
                                             float x0, float x1, float x2,
                                             float scale)
{
    const float u0 = x0 * scale, u1 = x1 * scale, u2 = x2 * scale;
    const float f0 = floorf(u0), f1 = floorf(u1), f2 = floorf(u2);
    const int   i0 = (int)f0,    i1 = (int)f1,    i2 = (int)f2;
    // d = ceil-floor is 1 when frac>0, else 0 -> diff == frac either way.
    const float d0 = u0 - f0, d1 = u1 - f1, d2 = u2 - f2;
    const float o0 = 1.0f - d0, o1 = 1.0f - d1, o2 = 1.0f - d2;

    // Pre-multiplied corner hash terms (wrapping int32, matches jnp/torch)
    const int pl0 = i0;                  const int ph0 = pl0 + 1;
    const int pl1 = i1 * PRIME1;         const int ph1 = pl1 + PRIME1;
    const int pl2 = i2 * PRIME2;         const int ph2 = pl2 + PRIME2;
    // frac==0 corners carry an exactly-zero weight, so hi = lo+1 is safe.

    float ax = 0.0f, ay = 0.0f;
    #pragma unroll
    for (int k = 0; k < 8; ++k) {
        const int a  = (k >> 2) & 1;
        const int b  = (k >> 1) & 1;
        const int c  = k & 1;
        const int h = (a ? ph0 : pl0) ^ (b ? ph1 : pl1) ^ (c ? ph2 : pl2);
        const int idx = h & TMASK;      // == mod 16384 for int32
        const float w = (a ? d0 : o0) * (b ? d1 : o1) * (c ? d2 : o2);
        const float2 v = table[idx];
        ax = fmaf(w, v.x, ax);
        ay = fmaf(w, v.y, ay);
    }
    return make_float2(ax, ay);
}

// ---------------------------------------------------------------------------
// Kernel 1: hash-grid gather, 4 points per thread. One CTA per (level,
// slice); the level's 128KB table (pre-scaled x8192) lives in shared memory.
//   - x loads: 3x LDG.128 per thread (48B), fully coalesced.
//   - 4 independent gather/FMA chains per thread.
//   - store: one uint4 STG.128 per thread (512B/warp), fp16x2 packed.
// ---------------------------------------------------------------------------
__global__ __launch_bounds__(NTHREADS, 1)
void hash_enc_kernel(const float* __restrict__ x,
                     const float* __restrict__ emb)
{
    extern __shared__ float2 table[];   // TSIZE float2 = 128KB
    const int level = blockIdx.y;

    // Cooperative table load, PRE-SCALED by 2^13 (exact in fp32).
    {
        const float4* src = (const float4*)(emb + (size_t)level * TSIZE * 2);
        float4* dst = (float4*)table;
        #pragma unroll
        for (int i = threadIdx.x; i < (TSIZE * 2) / 4; i += NTHREADS) {
            float4 v = src[i];
            v.x *= FSCALE; v.y *= FSCALE; v.z *= FSCALE; v.w *= FSCALE;
            dst[i] = v;
        }
    }
    __syncthreads();

    // Per-level resolution: N_l = Nmin * b^l (identical formula)
    const float bgrow = expf((logf(512.0f) - logf(16.0f)) * (1.0f / 16.0f));
    const float scale = 16.0f * powf(bgrow, (float)level);

    const float4* x4 = (const float4*)x;
    uint4* scr4 = (uint4*)(g_scr + (size_t)level * NPTS);

    const int stride = CTAS_PER_LVL * NTHREADS;
    for (int p = blockIdx.x * NTHREADS + threadIdx.x; p < NQUADS; p += stride) {
        // 12 floats = points 4p..4p+3, three aligned float4 loads
        const float4 va = x4[3 * p + 0];   // A0 A1 A2 B0
        const float4 vb = x4[3 * p + 1];   // B1 B2 C0 C1
        const float4 vc = x4[3 * p + 2];   // C2 D0 D1 D2

        const float2 rA = hash_point(table, va.x, va.y, va.z, scale);
        const float2 rB = hash_point(table, va.w, vb.x, vb.y, scale);
        const float2 rC = hash_point(table, vb.z, vb.w, vc.x, scale);
        const float2 rD = hash_point(table, vc.y, vc.z, vc.w, scale);

        // Values already scaled into fp16 normal range; pack in registers.
        scr4[p] = make_uint4(pack_f16x2(rA.x, rA.y), pack_f16x2(rB.x, rB.y),
                             pack_f16x2(rC.x, rC.y), pack_f16x2(rD.x, rD.y));
    }
}

// ---------------------------------------------------------------------------
// Kernel 2: (L, N) half2 -> (N, L*2) fp32 transpose. Thread t loads level l's
// half2 for point n0+t (warp: 128B contiguous), converts to fp32 (x1/8192,
// exact), tiles in smem, and writes 512B-contiguous STG.128 output rows.
// ---------------------------------------------------------------------------
__global__ __launch_bounds__(TPTS)
void transpose_kernel(float* __restrict__ out)
{
    __shared__ float2 tile[TPTS][TPITCH];   // 256 x 17 x 8B = 34.8KB

    const int n0 = blockIdx.x * TPTS;
    const int t  = threadIdx.x;

    #pragma unroll
    for (int l = 0; l < LVLS; ++l) {
        const __half2 h = g_scr[(size_t)l * NPTS + n0 + t];
        const float2 f = __half22float2(h);
        tile[t][l] = make_float2(f.x * INVSCALE, f.y * INVSCALE);
    }
    __syncthreads();

    // Store: warp writes 4 consecutive 128B output rows per pass.
    const int q  = t & 7;    // float4 (pair of levels) within the row
    const int pl = t >> 3;   // point-within-tile offset
    float4* out4 = (float4*)out;
    #pragma unroll
    for (int i = 0; i < TPTS / 32; ++i) {
        const int p = i * 32 + pl;
        const float2 a = tile[p][2 * q];
        const float2 b = tile[p][2 * q + 1];
        out4[(size_t)(n0 + p) * (LVLS / 2) + q] = make_float4(a.x, a.y, b.x, b.y);
    }
}

extern "C" void kernel_launch(void* const* d_in, const int* in_sizes, int n_in,
                              void* d_out, int out_size)
{
    const float* x;
    const float* emb;
    if (in_sizes[0] == NPTS * 3) {
        x = (const float*)d_in[0];
        emb = (const float*)d_in[1];
    } else {
        x = (const float*)d_in[1];
        emb = (const float*)d_in[0];
    }
    float* out = (float*)d_out;

    cudaFuncSetAttribute(hash_enc_kernel,
                         cudaFuncAttributeMaxDynamicSharedMemorySize,
                         TSIZE * 2 * (int)sizeof(float));

    dim3 grid(CTAS_PER_LVL, LVLS);   // 144 CTAs = one full wave @ 1 CTA/SM
    hash_enc_kernel<<<grid, NTHREADS, TSIZE * 2 * sizeof(float)>>>(x, emb);

    transpose_kernel<<<NPTS / TPTS, TPTS>>>(out);
}